// round 7
// baseline (speedup 1.0000x reference)
#include <cuda_runtime.h>
#include <cuda_bf16.h>

// PSAvgPooling: B=8, H=W=64, C=1152 (= 9 bins * 128), N=512 boxes/image,
// 3x3 bins x 3x3 crop samples, bilinear gather, weighted bin-average.
//
// R6 = R5 resubmit (R6 bench error was container infra, kernel never ran).
// R5: replace LDG.128 gathers (4 within-instruction wavefronts @2.07cyc replay)
//     with scalar LDG.32 gathers (1 wavefront each @1.0cyc). Lane = channel,
//     each lane covers channels {lane, lane+32, lane+64, lane+96}.
//     4 warps per box, samples split across warps, smem reduction.

namespace {

constexpr int Hh    = 64;
constexpr int Ww    = 64;
constexpr int Cc    = 1152;   // total channels
constexpr int Csz   = 128;    // channels per bin (Cc / 9)
constexpr int NB    = 3;      // bins per dim
constexpr int NSAMP = 81;     // 9 bins * 9 crop samples
constexpr int NWARP = 4;      // warps per box

__global__ __launch_bounds__(NWARP * 32, 8) void ps_pool_kernel(
    const float* __restrict__ img,    // [B, H, W, C]
    const float* __restrict__ boxes,  // [B*N, 4]  (y1,x1,y2,x2 normalized)
    const float* __restrict__ wts,    // [9]
    float* __restrict__ out,          // [B*N, 128]
    int nPerImage)
{
    __shared__ int4   s_off[NSAMP];          // element offsets of 4 bilinear corners (incl. bin*128)
    __shared__ float4 s_w[NSAMP];            // bilinear weights * bin weight * inside mask
    __shared__ float  s_red[NWARP][4][32];   // per-warp partials: [warp][k][lane] -> channel k*32+lane

    const int box_id = blockIdx.x;
    const int b      = box_id / nPerImage;
    const float* __restrict__ image = img + (size_t)b * (Hh * Ww * Cc);
    const float* bx = boxes + (size_t)box_id * 4;
    const int tid  = threadIdx.x;
    const int lane = tid & 31;
    const int warp = tid >> 5;

    const float y1 = bx[0], x1 = bx[1], y2 = bx[2], x2 = bx[3];
    const float step_y = (y2 - y1) * (1.0f / 3.0f);
    const float step_x = (x2 - x1) * (1.0f / 3.0f);

    // ---- Precompute 81 samples (element offsets + fused weights), one thread each ----
    if (tid < NSAMP) {
        const int s   = tid;
        const int by  = s / 27;
        const int bxn = (s / 9) % 3;
        const int py  = (s / 3) % 3;
        const int px  = s % 3;

        const float yy = (y1 + ((float)by + (float)py * 0.5f) * step_y) * (float)(Hh - 1);
        const float xx = (x1 + ((float)bxn + (float)px * 0.5f) * step_x) * (float)(Ww - 1);

        const float y0f = floorf(yy);
        const float x0f = floorf(xx);
        const float wy = yy - y0f;
        const float wx = xx - x0f;
        const int y0 = (int)y0f;
        const int x0 = (int)x0f;

        // reference clips each corner index independently
        const int y0c = min(max(y0,     0), Hh - 1);
        const int y1c = min(max(y0 + 1, 0), Hh - 1);
        const int x0c = min(max(x0,     0), Ww - 1);
        const int x1c = min(max(x0 + 1, 0), Ww - 1);

        const bool inside = (yy >= 0.0f) && (yy <= (float)(Hh - 1)) &&
                            (xx >= 0.0f) && (xx <= (float)(Ww - 1));
        const int bin = by * NB + bxn;
        const float wb = inside ? wts[bin] : 0.0f;
        const int cb = bin * Csz;

        s_off[s] = make_int4((y0c * Ww + x0c) * Cc + cb,
                             (y0c * Ww + x1c) * Cc + cb,
                             (y1c * Ww + x0c) * Cc + cb,
                             (y1c * Ww + x1c) * Cc + cb);
        s_w[s] = make_float4(wb * (1.0f - wy) * (1.0f - wx),
                             wb * (1.0f - wy) * wx,
                             wb * wy * (1.0f - wx),
                             wb * wy * wx);
    }
    __syncthreads();

    // ---- Each warp walks its slice of the 81 samples ----
    // Lane owns channels {lane, lane+32, lane+64, lane+96}: every LDG.32 covers
    // one full 128B line per warp (cross-LDG wavefronts, no replay penalty).
    const float* __restrict__ base = image + lane;
    const int s_begin = (warp * NSAMP) / NWARP;
    const int s_end   = ((warp + 1) * NSAMP) / NWARP;

    float acc0 = 0.f, acc1 = 0.f, acc2 = 0.f, acc3 = 0.f;

    #pragma unroll 2
    for (int s = s_begin; s < s_end; s++) {
        const int4   off = s_off[s];
        const float4 w   = s_w[s];

        // corner 0
        {
            const float* p = base + off.x;
            acc0 += w.x * __ldg(p);
            acc1 += w.x * __ldg(p + 32);
            acc2 += w.x * __ldg(p + 64);
            acc3 += w.x * __ldg(p + 96);
        }
        // corner 1
        {
            const float* p = base + off.y;
            acc0 += w.y * __ldg(p);
            acc1 += w.y * __ldg(p + 32);
            acc2 += w.y * __ldg(p + 64);
            acc3 += w.y * __ldg(p + 96);
        }
        // corner 2
        {
            const float* p = base + off.z;
            acc0 += w.z * __ldg(p);
            acc1 += w.z * __ldg(p + 32);
            acc2 += w.z * __ldg(p + 64);
            acc3 += w.z * __ldg(p + 96);
        }
        // corner 3
        {
            const float* p = base + off.w;
            acc0 += w.w * __ldg(p);
            acc1 += w.w * __ldg(p + 32);
            acc2 += w.w * __ldg(p + 64);
            acc3 += w.w * __ldg(p + 96);
        }
    }

    s_red[warp][0][lane] = acc0;
    s_red[warp][1][lane] = acc1;
    s_red[warp][2][lane] = acc2;
    s_red[warp][3][lane] = acc3;
    __syncthreads();

    // ---- First warp reduces the 4 partials and writes out (coalesced STG.32) ----
    if (warp == 0) {
        const float inv = 1.0f / 81.0f;  // mean over 9 samples, then /9 bins
        float* o = out + (size_t)box_id * Csz + lane;
        #pragma unroll
        for (int k = 0; k < 4; k++) {
            float v = s_red[0][k][lane] + s_red[1][k][lane]
                    + s_red[2][k][lane] + s_red[3][k][lane];
            o[k * 32] = v * inv;
        }
    }
}

} // namespace

extern "C" void kernel_launch(void* const* d_in, const int* in_sizes, int n_in,
                              void* d_out, int out_size) {
    const float* img   = (const float*)d_in[0];  // [B,64,64,1152] fp32
    const float* boxes = (const float*)d_in[1];  // [B,N,4] fp32
    const float* wts   = (const float*)d_in[2];  // [9] fp32
    float* out = (float*)d_out;                  // [B*N, 128] fp32

    const int B          = in_sizes[0] / (Hh * Ww * Cc);
    const int totalBoxes = in_sizes[1] / 4;
    const int nPerImage  = totalBoxes / B;

    ps_pool_kernel<<<totalBoxes, NWARP * 32>>>(img, boxes, wts, out, nPerImage);
}

// round 8
// speedup vs baseline: 1.1607x; 1.1607x over previous
#include <cuda_runtime.h>
#include <cuda_bf16.h>

// PSAvgPooling: B=8, H=W=64, C=1152 (= 9 bins * 128), N=512 boxes/image,
// 3x3 bins x 3x3 crop samples, bilinear gather, weighted bin-average.
//
// R7: LDG.64 gathers. Measured calibration:
//   LDG.128 (4 wf/instr): 41.4us  -> ~2.07 cyc per extra within-LDG wavefront
//   LDG.32  (1 wf/instr): 48.1us  -> >=1.8 cyc LSU floor per instr + ALU
//   LDG.64  (2 wf/instr): ~1.54 cyc per 128B line -> predicted ~34us.
// Lane owns channels {2*lane, 2*lane+1} and {64+2*lane, 64+2*lane+1}.
// 4 warps per box, samples split across warps, byte offsets, smem reduction.

namespace {

constexpr int Hh    = 64;
constexpr int Ww    = 64;
constexpr int Cc    = 1152;   // total channels
constexpr int Csz   = 128;    // channels per bin (Cc / 9)
constexpr int NB    = 3;      // bins per dim
constexpr int NSAMP = 81;     // 9 bins * 9 crop samples
constexpr int NWARP = 4;      // warps per box

__global__ __launch_bounds__(NWARP * 32, 8) void ps_pool_kernel(
    const float* __restrict__ img,    // [B, H, W, C]
    const float* __restrict__ boxes,  // [B*N, 4]  (y1,x1,y2,x2 normalized)
    const float* __restrict__ wts,    // [9]
    float* __restrict__ out,          // [B*N, 128]
    int nPerImage)
{
    __shared__ int4   s_off[NSAMP];          // BYTE offsets of 4 bilinear corners (incl. bin*128ch)
    __shared__ float4 s_w[NSAMP];            // bilinear weights * bin weight * inside mask
    __shared__ float2 s_red[NWARP][2][32];   // per-warp partials: [warp][half][lane]

    const int box_id = blockIdx.x;
    const int b      = box_id / nPerImage;
    const float* __restrict__ image = img + (size_t)b * (Hh * Ww * Cc);
    const float* bx = boxes + (size_t)box_id * 4;
    const int tid  = threadIdx.x;
    const int lane = tid & 31;
    const int warp = tid >> 5;

    const float y1 = bx[0], x1 = bx[1], y2 = bx[2], x2 = bx[3];
    const float step_y = (y2 - y1) * (1.0f / 3.0f);
    const float step_x = (x2 - x1) * (1.0f / 3.0f);

    // ---- Precompute 81 samples (byte offsets + fused weights), one thread each ----
    if (tid < NSAMP) {
        const int s   = tid;
        const int by  = s / 27;
        const int bxn = (s / 9) % 3;
        const int py  = (s / 3) % 3;
        const int px  = s % 3;

        const float yy = (y1 + ((float)by + (float)py * 0.5f) * step_y) * (float)(Hh - 1);
        const float xx = (x1 + ((float)bxn + (float)px * 0.5f) * step_x) * (float)(Ww - 1);

        const float y0f = floorf(yy);
        const float x0f = floorf(xx);
        const float wy = yy - y0f;
        const float wx = xx - x0f;
        const int y0 = (int)y0f;
        const int x0 = (int)x0f;

        // reference clips each corner index independently
        const int y0c = min(max(y0,     0), Hh - 1);
        const int y1c = min(max(y0 + 1, 0), Hh - 1);
        const int x0c = min(max(x0,     0), Ww - 1);
        const int x1c = min(max(x0 + 1, 0), Ww - 1);

        const bool inside = (yy >= 0.0f) && (yy <= (float)(Hh - 1)) &&
                            (xx >= 0.0f) && (xx <= (float)(Ww - 1));
        const int bin = by * NB + bxn;
        const float wb = inside ? wts[bin] : 0.0f;
        const int cb = bin * Csz;

        // byte offsets (float = 4 bytes)
        s_off[s] = make_int4(((y0c * Ww + x0c) * Cc + cb) * 4,
                             ((y0c * Ww + x1c) * Cc + cb) * 4,
                             ((y1c * Ww + x0c) * Cc + cb) * 4,
                             ((y1c * Ww + x1c) * Cc + cb) * 4);
        s_w[s] = make_float4(wb * (1.0f - wy) * (1.0f - wx),
                             wb * (1.0f - wy) * wx,
                             wb * wy * (1.0f - wx),
                             wb * wy * wx);
    }
    __syncthreads();

    // ---- Each warp walks its slice of the 81 samples ----
    // Lane owns channels {2*lane, 2*lane+1} (half A) and {64+2*lane, 64+2*lane+1} (half B).
    // Each LDG.64 covers one 256B line-aligned segment -> 2 wavefronts/instr.
    const char* __restrict__ base = (const char*)image + lane * 8;
    const int s_begin = (warp * NSAMP) / NWARP;
    const int s_end   = ((warp + 1) * NSAMP) / NWARP;

    float2 accA = make_float2(0.f, 0.f);
    float2 accB = make_float2(0.f, 0.f);

    #pragma unroll 2
    for (int s = s_begin; s < s_end; s++) {
        const int4   off = s_off[s];
        const float4 w   = s_w[s];

        const float2 a0 = __ldg((const float2*)(base + off.x));
        const float2 b0 = __ldg((const float2*)(base + off.x + 256));
        const float2 a1 = __ldg((const float2*)(base + off.y));
        const float2 b1 = __ldg((const float2*)(base + off.y + 256));
        const float2 a2 = __ldg((const float2*)(base + off.z));
        const float2 b2 = __ldg((const float2*)(base + off.z + 256));
        const float2 a3 = __ldg((const float2*)(base + off.w));
        const float2 b3 = __ldg((const float2*)(base + off.w + 256));

        accA.x += w.x * a0.x + w.y * a1.x + w.z * a2.x + w.w * a3.x;
        accA.y += w.x * a0.y + w.y * a1.y + w.z * a2.y + w.w * a3.y;
        accB.x += w.x * b0.x + w.y * b1.x + w.z * b2.x + w.w * b3.x;
        accB.y += w.x * b0.y + w.y * b1.y + w.z * b2.y + w.w * b3.y;
    }

    s_red[warp][0][lane] = accA;
    s_red[warp][1][lane] = accB;
    __syncthreads();

    // ---- First warp reduces the 4 partials and writes out (coalesced STG.64) ----
    if (warp == 0) {
        const float inv = 1.0f / 81.0f;  // mean over 9 samples, then /9 bins
        float2* o = (float2*)(out + (size_t)box_id * Csz) + lane;
        #pragma unroll
        for (int k = 0; k < 2; k++) {
            float2 v0 = s_red[0][k][lane];
            float2 v1 = s_red[1][k][lane];
            float2 v2 = s_red[2][k][lane];
            float2 v3 = s_red[3][k][lane];
            float2 v;
            v.x = (v0.x + v1.x + v2.x + v3.x) * inv;
            v.y = (v0.y + v1.y + v2.y + v3.y) * inv;
            o[k * 32] = v;
        }
    }
}

} // namespace

extern "C" void kernel_launch(void* const* d_in, const int* in_sizes, int n_in,
                              void* d_out, int out_size) {
    const float* img   = (const float*)d_in[0];  // [B,64,64,1152] fp32
    const float* boxes = (const float*)d_in[1];  // [B,N,4] fp32
    const float* wts   = (const float*)d_in[2];  // [9] fp32
    float* out = (float*)d_out;                  // [B*N, 128] fp32

    const int B          = in_sizes[0] / (Hh * Ww * Cc);
    const int totalBoxes = in_sizes[1] / 4;
    const int nPerImage  = totalBoxes / B;

    ps_pool_kernel<<<totalBoxes, NWARP * 32>>>(img, boxes, wts, out, nPerImage);
}